// round 11
// baseline (speedup 1.0000x reference)
#include <cuda_runtime.h>
#include <cuda_bf16.h>
#include <cstdint>

// ---------------------------------------------------------------------------
// SR_GNN via mma.sync tf32 (HMMA), fragment-major A smem.
//   hidden = emb[x]                       (exact + rounded copies)
//   big    = hidden_r @ [w_in|w_out|w_hh]^T + bias
//            cols<256 -> ht (transposed per batch, ROUNDED); cols>=256 -> gh
//   inputs = [A[:,:, :N]@h_in + b_iah | A[:,:,N:]@h_out + b_oah]  (ROUNDED)
//   gi     = inputs @ w_ih^T + b_ih
//   out    = gates(gi, gh, hidden)
// ---------------------------------------------------------------------------

#define Bsz 512
#define Nn  200
#define Mrows (Bsz*Nn)                 // 102400
#define HT_HALF (512*128*200)

__device__ float g_hidden  [(size_t)Mrows * 128];
__device__ float g_hidden_r[(size_t)Mrows * 128];
__device__ float g_ht    [(size_t)2 * HT_HALF];
__device__ float g_gh    [(size_t)Mrows * 384];
__device__ float g_inputs[(size_t)Mrows * 256];
__device__ float g_gi    [(size_t)Mrows * 384];
__device__ float g_W1    [640 * 128];
__device__ float g_W2r   [384 * 256];
__device__ float g_bias1 [640];

// ---------------- helpers ----------------
__device__ __forceinline__ uint32_t smem_u32(const void* p) {
    uint32_t a;
    asm("{ .reg .u64 t; cvta.to.shared.u64 t, %1; cvt.u32.u64 %0, t; }" : "=r"(a) : "l"(p));
    return a;
}
__device__ __forceinline__ uint32_t cvt_tf32(float f) {
    uint32_t r;
    asm("cvt.rna.tf32.f32 %0, %1;" : "=r"(r) : "f"(f));
    return r;
}
__device__ __forceinline__ float round_tf32(float f) { return __uint_as_float(cvt_tf32(f)); }

__device__ __forceinline__ void mma8(float* d, const uint32_t* a, const uint32_t* b) {
    asm volatile("mma.sync.aligned.m16n8k8.row.col.f32.tf32.tf32.f32 "
        "{%0,%1,%2,%3}, {%4,%5,%6,%7}, {%8,%9}, {%0,%1,%2,%3};"
        : "+f"(d[0]), "+f"(d[1]), "+f"(d[2]), "+f"(d[3])
        : "r"(a[0]), "r"(a[1]), "r"(a[2]), "r"(a[3]), "r"(b[0]), "r"(b[1]));
}
#define CP_ASYNC(dst, src, sz) \
    asm volatile("cp.async.cg.shared.global [%0], [%1], 16, %2;" :: "r"(dst), "l"(src), "r"(sz))
#define CP_COMMIT()  asm volatile("cp.async.commit_group;" ::: "memory")
#define CP_WAIT(n)   asm volatile("cp.async.wait_group %0;" :: "n"(n) : "memory")

// ---------------- prep / gather ----------------
__global__ void prep_kernel(const float* __restrict__ w_in, const float* __restrict__ b_in,
                            const float* __restrict__ w_out, const float* __restrict__ b_out,
                            const float* __restrict__ w_ih,
                            const float* __restrict__ w_hh, const float* __restrict__ b_hh) {
    int idx = blockIdx.x * blockDim.x + threadIdx.x;
    if (idx < 640 * 128) {
        int j = idx / 128, k = idx % 128;
        float v;
        if (j < 128)      v = w_in [j * 128 + k];
        else if (j < 256) v = w_out[(j - 128) * 128 + k];
        else              v = w_hh [(j - 256) * 128 + k];
        g_W1[idx] = round_tf32(v);
    } else if (idx < 640 * 128 + 384 * 256) {
        int t = idx - 640 * 128;
        g_W2r[t] = round_tf32(w_ih[t]);
    } else if (idx < 640 * 128 + 384 * 256 + 640) {
        int j = idx - 640 * 128 - 384 * 256;
        g_bias1[j] = (j < 128) ? b_in[j] : (j < 256) ? b_out[j - 128] : b_hh[j - 256];
    }
}

__global__ void gather_kernel(const int* __restrict__ x, const float* __restrict__ emb) {
    long long t = (long long)blockIdx.x * blockDim.x + threadIdx.x;
    const long long total4 = (long long)Mrows * 32;
    if (t >= total4) return;
    int m = (int)(t >> 5), c = (int)(t & 31);
    int v = __ldg(&x[m]);
    float4 e = ((const float4*)emb)[(long long)v * 32 + c];
    ((float4*)g_hidden)[t] = e;
    float4 r;
    r.x = round_tf32(e.x); r.y = round_tf32(e.y);
    r.z = round_tf32(e.z); r.w = round_tf32(e.w);
    ((float4*)g_hidden_r)[t] = r;
}

// ---------------------------------------------------------------------------
// GEMM: block 128x128, K-chunk 32, 8 warps (2x4), warp tile 64x32.
// A: fragment-major smem (uint4 slots = a-frag layout), LDG->(cvt)->STS,
//    double buffered. B: row-major padded smem via cp.async, triple buffered.
// MODE 1: stage3; MODE 2: stage4 merged halves (cvt A at producer); MODE 0: stage5
// ---------------------------------------------------------------------------
#define LDP 36
#define ABUF_BYTES 16384                 // 1024 uint4 slots
#define BBUF_BYTES (128 * LDP * 4)       // 18432
#define SMEM_BYTES (2 * ABUF_BYTES + 3 * BBUF_BYTES)   // 88064

// A frag-major slot: s = ((ks*8 + g16)*8 + (gid ^ (ks<<1)))*4 + tig
// float within slot: comp = kh*2 + hm
template <bool DO_CVT>
__device__ __forceinline__ void produceA(float* sA, const float* __restrict__ Asrc,
                                         int lda, int a_rows, int k0, int K, int tid) {
    #pragma unroll
    for (int it = 0; it < 4; ++it) {
        int item = it * 256 + tid;
        int row = item >> 3, c4 = item & 7;
        int gk = k0 + c4 * 4;
        float4 v = make_float4(0.f, 0.f, 0.f, 0.f);
        if (row < a_rows && gk < K)
            v = *(const float4*)(Asrc + (long long)row * lda + gk);
        int g16 = row >> 4, gid = row & 7, hm = (row >> 3) & 1;
        int ks = c4 >> 1, kh = c4 & 1;
        int gidx = gid ^ (ks << 1);
        float* base = sA + ((((ks * 8 + g16) * 8 + gidx) * 4) << 2) + kh * 2 + hm;
        float vv[4] = {v.x, v.y, v.z, v.w};
        #pragma unroll
        for (int f = 0; f < 4; ++f)
            base[f * 4] = DO_CVT ? round_tf32(vv[f]) : vv[f];
    }
}

__device__ __forceinline__ void produceB(uint32_t sb, const float* __restrict__ Bsrc,
                                         int ldb, int k0, int K, int tid) {
    #pragma unroll
    for (int it = 0; it < 4; ++it) {
        int item = it * 256 + tid;
        int row = item >> 3, c4 = item & 7;
        int gk = k0 + c4 * 4;
        bool ok = (gk < K);
        const float* src = ok ? (Bsrc + (long long)row * ldb + gk) : Bsrc;
        CP_ASYNC(sb + (uint32_t)(row * LDP + c4 * 4) * 4, src, ok ? 16 : 0);
    }
}

template <int MODE>
__global__ __launch_bounds__(256, 2)
void mma_gemm(const float* __restrict__ A, int lda, int Arows, long long sA,
              const float* __restrict__ Bm, int ldb, long long sB,
              const float* __restrict__ bias, const float* __restrict__ bias2,
              float* __restrict__ C, int ldc, long long sC, int cshift,
              float* __restrict__ ht, int K) {
    extern __shared__ float smemf[];
    char* smem_c = (char*)smemf;
    const uint32_t sbase = smem_u32(smemf);
    const int tid = threadIdx.x;
    const int wid = tid >> 5, lane = tid & 31;
    const int gid = lane >> 2, tig = lane & 3;
    const int wm0 = (wid >> 2) * 64;
    const int wn0 = (wid & 3) * 32;

    int n0;
    if (MODE == 2) {
        const int half = blockIdx.x;
        A   += (long long)blockIdx.z * sA + half * Nn;
        Bm  += (size_t)half * HT_HALF + (long long)blockIdx.z * sB;
        bias = half ? bias2 : bias;
        C   += (long long)blockIdx.z * sC + half * 128;
        n0 = 0;
    } else {
        A  += (long long)blockIdx.z * sA;
        Bm += (long long)blockIdx.z * sB;
        C  += (long long)blockIdx.z * sC;
        n0 = blockIdx.x * 128;
    }
    const int m0 = blockIdx.y * 128;
    const float* Asrc = A + (long long)m0 * lda;
    const float* Bsrc = Bm + (long long)n0 * ldb;
    const int a_rows = (Arows - m0) < 128 ? (Arows - m0) : 128;

    float acc[4][4][4];
    #pragma unroll
    for (int i = 0; i < 4; ++i)
        #pragma unroll
        for (int j = 0; j < 4; ++j)
            #pragma unroll
            for (int q = 0; q < 4; ++q) acc[i][j][q] = 0.f;

    float* aBuf0 = smemf;
    float* aBuf1 = (float*)(smem_c + ABUF_BYTES);
    const uint32_t sbB0 = sbase + 2 * ABUF_BYTES;

    const int nk = (K + 31) / 32;
    // prologue
    produceB(sbB0, Bsrc, ldb, 0, K, tid);
    CP_COMMIT();
    produceB(sbB0 + BBUF_BYTES, Bsrc, ldb, 32, K, tid);   // nk>=4 always here
    CP_COMMIT();
    produceA<MODE == 2>(aBuf0, Asrc, lda, a_rows, 0, K, tid);
    CP_WAIT(1);
    __syncthreads();

    for (int ck = 0; ck < nk; ++ck) {
        if (ck + 2 < nk) {
            int b3 = (ck + 2) % 3;
            produceB(sbB0 + (uint32_t)b3 * BBUF_BYTES, Bsrc, ldb, (ck + 2) * 32, K, tid);
            CP_COMMIT();
        }
        const uint4*  Af   = (const uint4*)((ck & 1) ? aBuf1 : aBuf0);
        const float*  Bs_f = (const float*)(smem_c + 2 * ABUF_BYTES + (ck % 3) * BBUF_BYTES);
        const int k0 = ck * 32;

        #pragma unroll
        for (int ks = 0; ks < 4; ++ks) {
            if (k0 + ks * 8 < K) {
                uint4 a4[4];
                uint32_t bf[4][2];
                const int gidx = gid ^ (ks << 1);
                #pragma unroll
                for (int tm = 0; tm < 4; ++tm) {
                    if (wm0 + tm * 16 < a_rows)
                        a4[tm] = Af[((ks * 8 + (wm0 >> 4) + tm) * 8 + gidx) * 4 + tig];
                }
                #pragma unroll
                for (int tn = 0; tn < 4; ++tn) {
                    const float* p = Bs_f + (wn0 + tn * 8 + gid) * LDP + ks * 8 + tig;
                    bf[tn][0] = __float_as_uint(p[0]);
                    bf[tn][1] = __float_as_uint(p[4]);
                }
                #pragma unroll
                for (int tm = 0; tm < 4; ++tm) {
                    if (wm0 + tm * 16 < a_rows) {
                        #pragma unroll
                        for (int tn = 0; tn < 4; ++tn)
                            mma8(acc[tm][tn], (const uint32_t*)&a4[tm], bf[tn]);
                    }
                }
            }
        }

        if (ck + 1 < nk)
            produceA<MODE == 2>((ck & 1) ? aBuf0 : aBuf1, Asrc, lda, a_rows, (ck + 1) * 32, K, tid);
        if (ck + 2 < nk) { CP_WAIT(1); } else { CP_WAIT(0); }
        __syncthreads();
    }

    // ---- epilogue ----
    #pragma unroll
    for (int tm = 0; tm < 4; ++tm) {
        const int r0 = m0 + wm0 + tm * 16 + gid;
        #pragma unroll
        for (int half_m = 0; half_m < 2; ++half_m) {
            const int gm = r0 + half_m * 8;
            if (gm >= Arows) continue;
            #pragma unroll
            for (int tn = 0; tn < 4; ++tn) {
                const int cb = n0 + wn0 + tn * 8 + tig * 2;
                float v0 = acc[tm][tn][half_m * 2 + 0] + bias[cb];
                float v1 = acc[tm][tn][half_m * 2 + 1] + bias[cb + 1];
                if (MODE == 1 && n0 < 256) {
                    int b = gm / 200, i = gm - b * 200;
                    int half = cb >> 7, jj = cb & 127;
                    float* base = ht + (size_t)half * HT_HALF + (size_t)b * 25600;
                    base[jj * 200 + i]       = round_tf32(v0);
                    base[(jj + 1) * 200 + i] = round_tf32(v1);
                } else if (MODE == 2) {
                    *(float2*)(C + (size_t)gm * ldc + cb) =
                        make_float2(round_tf32(v0), round_tf32(v1));
                } else {
                    *(float2*)(C + (size_t)gm * ldc + (cb - cshift)) = make_float2(v0, v1);
                }
            }
        }
    }
}

// ---------------- gates ----------------
__global__ void gates_kernel(float* __restrict__ out) {
    long long idx = (long long)blockIdx.x * blockDim.x + threadIdx.x;
    const long long total = (long long)Mrows * 128;
    if (idx >= total) return;
    int row = (int)(idx >> 7);
    int d   = (int)(idx & 127);

    const float* gi = g_gi + (long long)row * 384;
    const float* gh = g_gh + (long long)row * 384;
    float i_r = gi[d], i_i = gi[128 + d], i_n = gi[256 + d];
    float h_r = gh[d], h_i = gh[128 + d], h_n = gh[256 + d];
    float hid = g_hidden[(long long)row * 128 + d];

    float gate_input  = 1.f / (1.f + expf(-(i_i + h_i)));
    float gate_reset  = 1.f / (1.f + expf(-(i_r + h_r)));
    float gate_output = tanhf(i_n + gate_reset * h_n);
    out[idx] = gate_output + gate_input * (hid - gate_output);
}

// ---------------------------------------------------------------------------
extern "C" void kernel_launch(void* const* d_in, const int* in_sizes, int n_in,
                              void* d_out, int out_size) {
    const int*   x     = (const int*)  d_in[0];
    const float* Amat  = (const float*)d_in[1];
    const float* emb   = (const float*)d_in[2];
    const float* w_in  = (const float*)d_in[3];
    const float* b_in  = (const float*)d_in[4];
    const float* w_out = (const float*)d_in[5];
    const float* b_out = (const float*)d_in[6];
    const float* w_ih  = (const float*)d_in[7];
    const float* b_ih  = (const float*)d_in[8];
    const float* w_hh  = (const float*)d_in[9];
    const float* b_hh  = (const float*)d_in[10];
    const float* b_iah = (const float*)d_in[11];
    const float* b_oah = (const float*)d_in[12];
    float* out = (float*)d_out;

    float *p_hidden_r, *p_ht, *p_gh, *p_inputs, *p_gi, *p_W1, *p_W2r, *p_bias1;
    cudaGetSymbolAddress((void**)&p_hidden_r, g_hidden_r);
    cudaGetSymbolAddress((void**)&p_ht,     g_ht);
    cudaGetSymbolAddress((void**)&p_gh,     g_gh);
    cudaGetSymbolAddress((void**)&p_inputs, g_inputs);
    cudaGetSymbolAddress((void**)&p_gi,     g_gi);
    cudaGetSymbolAddress((void**)&p_W1,     g_W1);
    cudaGetSymbolAddress((void**)&p_W2r,    g_W2r);
    cudaGetSymbolAddress((void**)&p_bias1,  g_bias1);

    cudaFuncSetAttribute(mma_gemm<0>, cudaFuncAttributeMaxDynamicSharedMemorySize, SMEM_BYTES);
    cudaFuncSetAttribute(mma_gemm<1>, cudaFuncAttributeMaxDynamicSharedMemorySize, SMEM_BYTES);
    cudaFuncSetAttribute(mma_gemm<2>, cudaFuncAttributeMaxDynamicSharedMemorySize, SMEM_BYTES);

    // 1. prep
    {
        int total = 640 * 128 + 384 * 256 + 640;
        prep_kernel<<<(total + 255) / 256, 256>>>(w_in, b_in, w_out, b_out, w_ih, w_hh, b_hh);
    }
    // 2. gather
    {
        long long total4 = (long long)Mrows * 32;
        gather_kernel<<<(int)((total4 + 255) / 256), 256>>>(x, emb);
    }
    // 3. big = hidden_r @ W1^T + bias1
    mma_gemm<1><<<dim3(5, Mrows / 128, 1), 256, SMEM_BYTES>>>(
        p_hidden_r, 128, Mrows, 0,
        p_W1, 128, 0,
        p_bias1, nullptr,
        p_gh, 384, 0, 256,
        p_ht, 128);
    // 4. inputs = [A_lo@h_in + b_iah | A_hi@h_out + b_oah]
    mma_gemm<2><<<dim3(2, 2, Bsz), 256, SMEM_BYTES>>>(
        Amat, 2 * Nn, Nn, (long long)Nn * 2 * Nn,
        p_ht, Nn, 25600,
        b_iah, b_oah,
        p_inputs, 256, (long long)Nn * 256, 0,
        nullptr, Nn);
    // 5. gi = inputs @ w_ih^T + b_ih
    mma_gemm<0><<<dim3(3, Mrows / 128, 1), 256, SMEM_BYTES>>>(
        p_inputs, 256, Mrows, 0,
        p_W2r, 256, 0,
        b_ih, nullptr,
        p_gi, 384, 0, 0,
        nullptr, 256);
    // 6. gates
    {
        long long total = (long long)Mrows * 128;
        gates_kernel<<<(int)((total + 255) / 256), 256>>>(out);
    }
}

// round 13
// speedup vs baseline: 1.1850x; 1.1850x over previous
#include <cuda_runtime.h>
#include <cuda_bf16.h>
#include <cstdint>

// ---------------------------------------------------------------------------
// SR_GNN via mma.sync tf32 (HMMA). Block 256x128, warp tile 64x64, 3-stage
// cp.async pipeline (all operands async; R11's sync producer regressed).
//   hidden = emb[x]                       (exact + rounded copies)
//   big    = hidden_r @ [w_in|w_out|w_hh]^T + bias
//            cols<256 -> ht (transposed per batch, ROUNDED); cols>=256 -> gh
//   inputs = [A[:,:, :N]@h_in + b_iah | A[:,:,N:]@h_out + b_oah]  (ROUNDED)
//   gi     = inputs @ w_ih^T + b_ih
//   out    = gates(gi, gh, hidden)
// ---------------------------------------------------------------------------

#define Bsz 512
#define Nn  200
#define Mrows (Bsz*Nn)                 // 102400
#define HT_HALF (512*128*200)

__device__ float g_hidden  [(size_t)Mrows * 128];
__device__ float g_hidden_r[(size_t)Mrows * 128];
__device__ float g_ht    [(size_t)2 * HT_HALF];
__device__ float g_gh    [(size_t)Mrows * 384];
__device__ float g_inputs[(size_t)Mrows * 256];
__device__ float g_gi    [(size_t)Mrows * 384];
__device__ float g_W1    [640 * 128];
__device__ float g_W2r   [384 * 256];
__device__ float g_bias1 [640];

// ---------------- helpers ----------------
__device__ __forceinline__ uint32_t smem_u32(const void* p) {
    uint32_t a;
    asm("{ .reg .u64 t; cvta.to.shared.u64 t, %1; cvt.u32.u64 %0, t; }" : "=r"(a) : "l"(p));
    return a;
}
__device__ __forceinline__ uint32_t cvt_tf32(float f) {
    uint32_t r;
    asm("cvt.rna.tf32.f32 %0, %1;" : "=r"(r) : "f"(f));
    return r;
}
__device__ __forceinline__ float round_tf32(float f) { return __uint_as_float(cvt_tf32(f)); }

__device__ __forceinline__ void mma8(float* d, const uint32_t* a, const uint32_t* b) {
    asm volatile("mma.sync.aligned.m16n8k8.row.col.f32.tf32.tf32.f32 "
        "{%0,%1,%2,%3}, {%4,%5,%6,%7}, {%8,%9}, {%0,%1,%2,%3};"
        : "+f"(d[0]), "+f"(d[1]), "+f"(d[2]), "+f"(d[3])
        : "r"(a[0]), "r"(a[1]), "r"(a[2]), "r"(a[3]), "r"(b[0]), "r"(b[1]));
}
#define CP_ASYNC(dst, src, sz) \
    asm volatile("cp.async.cg.shared.global [%0], [%1], 16, %2;" :: "r"(dst), "l"(src), "r"(sz))
#define CP_COMMIT()  asm volatile("cp.async.commit_group;" ::: "memory")
#define CP_WAIT(n)   asm volatile("cp.async.wait_group %0;" :: "n"(n) : "memory")

// ---------------- prep / gather ----------------
__global__ void prep_kernel(const float* __restrict__ w_in, const float* __restrict__ b_in,
                            const float* __restrict__ w_out, const float* __restrict__ b_out,
                            const float* __restrict__ w_ih,
                            const float* __restrict__ w_hh, const float* __restrict__ b_hh) {
    int idx = blockIdx.x * blockDim.x + threadIdx.x;
    if (idx < 640 * 128) {
        int j = idx / 128, k = idx % 128;
        float v;
        if (j < 128)      v = w_in [j * 128 + k];
        else if (j < 256) v = w_out[(j - 128) * 128 + k];
        else              v = w_hh [(j - 256) * 128 + k];
        g_W1[idx] = round_tf32(v);
    } else if (idx < 640 * 128 + 384 * 256) {
        int t = idx - 640 * 128;
        g_W2r[t] = round_tf32(w_ih[t]);
    } else if (idx < 640 * 128 + 384 * 256 + 640) {
        int j = idx - 640 * 128 - 384 * 256;
        g_bias1[j] = (j < 128) ? b_in[j] : (j < 256) ? b_out[j - 128] : b_hh[j - 256];
    }
}

__global__ void gather_kernel(const int* __restrict__ x, const float* __restrict__ emb) {
    long long t = (long long)blockIdx.x * blockDim.x + threadIdx.x;
    const long long total4 = (long long)Mrows * 32;
    if (t >= total4) return;
    int m = (int)(t >> 5), c = (int)(t & 31);
    int v = __ldg(&x[m]);
    float4 e = ((const float4*)emb)[(long long)v * 32 + c];
    ((float4*)g_hidden)[t] = e;
    float4 r;
    r.x = round_tf32(e.x); r.y = round_tf32(e.y);
    r.z = round_tf32(e.z); r.w = round_tf32(e.w);
    ((float4*)g_hidden_r)[t] = r;
}

// ---------------------------------------------------------------------------
// GEMM: block 256x128, K-chunk 32, 8 warps (4x2), warp tile 64x64.
// Row-major padded smem (LDP=36), all loads cp.async, 3-stage pipeline.
// MODE 1: stage3 split epilogue; MODE 2: stage4 merged halves (cvt A frags,
// rounded store); MODE 0: stage5 plain.
// ---------------------------------------------------------------------------
#define LDP 36
#define A_F (256 * LDP)                 // A tile floats
#define B_F (128 * LDP)
#define STAGE_F (A_F + B_F)             // 13824 floats = 55296 B
#define SMEM_BYTES (3 * STAGE_F * 4)    // 165888 B

__device__ __forceinline__ void load_stage(uint32_t sb, const float* __restrict__ A, int lda,
                                           int a_rows, const float* __restrict__ B, int ldb,
                                           int k0, int K, int tid) {
    // A: 256 rows x 8 float4
    #pragma unroll
    for (int it = 0; it < 8; ++it) {
        int item = it * 256 + tid;
        int row = item >> 3, c4 = item & 7;
        int gk = k0 + c4 * 4;
        bool ok = (row < a_rows) && (gk < K);
        const float* src = ok ? (A + (long long)row * lda + gk) : A;
        CP_ASYNC(sb + (uint32_t)(row * LDP + c4 * 4) * 4, src, ok ? 16 : 0);
    }
    // B: 128 rows x 8 float4
    #pragma unroll
    for (int it = 0; it < 4; ++it) {
        int item = it * 256 + tid;
        int row = item >> 3, c4 = item & 7;
        int gk = k0 + c4 * 4;
        bool ok = (gk < K);
        const float* src = ok ? (B + (long long)row * ldb + gk) : B;
        CP_ASYNC(sb + (uint32_t)(A_F + row * LDP + c4 * 4) * 4, src, ok ? 16 : 0);
    }
}

template <int MODE>
__global__ __launch_bounds__(256)
void mma_gemm(const float* __restrict__ A, int lda, int Arows, long long sA,
              const float* __restrict__ Bm, int ldb, long long sB,
              const float* __restrict__ bias, const float* __restrict__ bias2,
              float* __restrict__ C, int ldc, long long sC, int cshift,
              float* __restrict__ ht, int K) {
    extern __shared__ float smemf[];
    const uint32_t sbase = smem_u32(smemf);
    const int tid = threadIdx.x;
    const int wid = tid >> 5, lane = tid & 31;
    const int gid = lane >> 2, tig = lane & 3;
    const int wm0 = (wid >> 1) * 64;       // 0,64,128,192
    const int wn0 = (wid & 1) * 64;        // 0,64

    int n0;
    if (MODE == 2) {
        const int half = blockIdx.x;
        A   += (long long)blockIdx.z * sA + half * Nn;
        Bm  += (size_t)half * HT_HALF + (long long)blockIdx.z * sB;
        bias = half ? bias2 : bias;
        C   += (long long)blockIdx.z * sC + half * 128;
        n0 = 0;
    } else {
        A  += (long long)blockIdx.z * sA;
        Bm += (long long)blockIdx.z * sB;
        C  += (long long)blockIdx.z * sC;
        n0 = blockIdx.x * 128;
    }
    const int m0 = blockIdx.y * 256;
    const float* Asrc = A + (long long)m0 * lda;
    const float* Bsrc = Bm + (long long)n0 * ldb;
    const int a_rows = (Arows - m0) < 256 ? (Arows - m0) : 256;

    float acc[4][8][4];
    #pragma unroll
    for (int i = 0; i < 4; ++i)
        #pragma unroll
        for (int j = 0; j < 8; ++j)
            #pragma unroll
            for (int q = 0; q < 4; ++q) acc[i][j][q] = 0.f;

    const int nk = (K + 31) / 32;
    // prologue (nk >= 4 for all stages)
    load_stage(sbase, Asrc, lda, a_rows, Bsrc, ldb, 0, K, tid);
    CP_COMMIT();
    load_stage(sbase + (uint32_t)STAGE_F * 4, Asrc, lda, a_rows, Bsrc, ldb, 32, K, tid);
    CP_COMMIT();
    CP_WAIT(1);
    __syncthreads();

    for (int ck = 0; ck < nk; ++ck) {
        if (ck + 2 < nk) {
            load_stage(sbase + (uint32_t)((ck + 2) % 3) * STAGE_F * 4,
                       Asrc, lda, a_rows, Bsrc, ldb, (ck + 2) * 32, K, tid);
            CP_COMMIT();
        }
        const float* As_f = smemf + (ck % 3) * STAGE_F;
        const float* Bs_f = As_f + A_F;
        const int k0 = ck * 32;

        #pragma unroll
        for (int ks = 0; ks < 4; ++ks) {
            if (k0 + ks * 8 < K) {                       // warp-uniform; exact (zfill)
                uint32_t af[4][4], bf[8][2];
                #pragma unroll
                for (int tm = 0; tm < 4; ++tm) {
                    const float* p = As_f + (wm0 + tm * 16 + gid) * LDP + ks * 8 + tig;
                    if (MODE == 2) {
                        af[tm][0] = cvt_tf32(p[0]);
                        af[tm][1] = cvt_tf32(p[8 * LDP]);
                        af[tm][2] = cvt_tf32(p[4]);
                        af[tm][3] = cvt_tf32(p[8 * LDP + 4]);
                    } else {
                        af[tm][0] = __float_as_uint(p[0]);
                        af[tm][1] = __float_as_uint(p[8 * LDP]);
                        af[tm][2] = __float_as_uint(p[4]);
                        af[tm][3] = __float_as_uint(p[8 * LDP + 4]);
                    }
                }
                #pragma unroll
                for (int tn = 0; tn < 8; ++tn) {
                    const float* p = Bs_f + (wn0 + tn * 8 + gid) * LDP + ks * 8 + tig;
                    bf[tn][0] = __float_as_uint(p[0]);
                    bf[tn][1] = __float_as_uint(p[4]);
                }
                #pragma unroll
                for (int tm = 0; tm < 4; ++tm) {
                    if (wm0 + tm * 16 < a_rows) {        // warp-uniform; exact (zfill)
                        #pragma unroll
                        for (int tn = 0; tn < 8; ++tn)
                            mma8(acc[tm][tn], af[tm], bf[tn]);
                    }
                }
            }
        }

        if (ck + 2 < nk) { CP_WAIT(2); } else if (ck + 1 < nk) { CP_WAIT(1); } else { CP_WAIT(0); }
        __syncthreads();
    }

    // ---- epilogue ----
    #pragma unroll
    for (int tm = 0; tm < 4; ++tm) {
        const int r0 = m0 + wm0 + tm * 16 + gid;
        #pragma unroll
        for (int half_m = 0; half_m < 2; ++half_m) {
            const int gm = r0 + half_m * 8;
            if (gm >= Arows) continue;
            #pragma unroll
            for (int tn = 0; tn < 8; ++tn) {
                const int cb = n0 + wn0 + tn * 8 + tig * 2;
                float v0 = acc[tm][tn][half_m * 2 + 0] + bias[cb];
                float v1 = acc[tm][tn][half_m * 2 + 1] + bias[cb + 1];
                if (MODE == 1 && n0 < 256) {
                    int b = gm / 200, i = gm - b * 200;
                    int half = cb >> 7, jj = cb & 127;
                    float* base = ht + (size_t)half * HT_HALF + (size_t)b * 25600;
                    base[jj * 200 + i]       = round_tf32(v0);
                    base[(jj + 1) * 200 + i] = round_tf32(v1);
                } else if (MODE == 2) {
                    *(float2*)(C + (size_t)gm * ldc + cb) =
                        make_float2(round_tf32(v0), round_tf32(v1));
                } else {
                    *(float2*)(C + (size_t)gm * ldc + (cb - cshift)) = make_float2(v0, v1);
                }
            }
        }
    }
}

// ---------------- gates ----------------
__global__ void gates_kernel(float* __restrict__ out) {
    long long idx = (long long)blockIdx.x * blockDim.x + threadIdx.x;
    const long long total = (long long)Mrows * 128;
    if (idx >= total) return;
    int row = (int)(idx >> 7);
    int d   = (int)(idx & 127);

    const float* gi = g_gi + (long long)row * 384;
    const float* gh = g_gh + (long long)row * 384;
    float i_r = gi[d], i_i = gi[128 + d], i_n = gi[256 + d];
    float h_r = gh[d], h_i = gh[128 + d], h_n = gh[256 + d];
    float hid = g_hidden[(long long)row * 128 + d];

    float gate_input  = 1.f / (1.f + expf(-(i_i + h_i)));
    float gate_reset  = 1.f / (1.f + expf(-(i_r + h_r)));
    float gate_output = tanhf(i_n + gate_reset * h_n);
    out[idx] = gate_output + gate_input * (hid - gate_output);
}

// ---------------------------------------------------------------------------
extern "C" void kernel_launch(void* const* d_in, const int* in_sizes, int n_in,
                              void* d_out, int out_size) {
    const int*   x     = (const int*)  d_in[0];
    const float* Amat  = (const float*)d_in[1];
    const float* emb   = (const float*)d_in[2];
    const float* w_in  = (const float*)d_in[3];
    const float* b_in  = (const float*)d_in[4];
    const float* w_out = (const float*)d_in[5];
    const float* b_out = (const float*)d_in[6];
    const float* w_ih  = (const float*)d_in[7];
    const float* b_ih  = (const float*)d_in[8];
    const float* w_hh  = (const float*)d_in[9];
    const float* b_hh  = (const float*)d_in[10];
    const float* b_iah = (const float*)d_in[11];
    const float* b_oah = (const float*)d_in[12];
    float* out = (float*)d_out;

    float *p_hidden_r, *p_ht, *p_gh, *p_inputs, *p_gi, *p_W1, *p_W2r, *p_bias1;
    cudaGetSymbolAddress((void**)&p_hidden_r, g_hidden_r);
    cudaGetSymbolAddress((void**)&p_ht,     g_ht);
    cudaGetSymbolAddress((void**)&p_gh,     g_gh);
    cudaGetSymbolAddress((void**)&p_inputs, g_inputs);
    cudaGetSymbolAddress((void**)&p_gi,     g_gi);
    cudaGetSymbolAddress((void**)&p_W1,     g_W1);
    cudaGetSymbolAddress((void**)&p_W2r,    g_W2r);
    cudaGetSymbolAddress((void**)&p_bias1,  g_bias1);

    cudaFuncSetAttribute(mma_gemm<0>, cudaFuncAttributeMaxDynamicSharedMemorySize, SMEM_BYTES);
    cudaFuncSetAttribute(mma_gemm<1>, cudaFuncAttributeMaxDynamicSharedMemorySize, SMEM_BYTES);
    cudaFuncSetAttribute(mma_gemm<2>, cudaFuncAttributeMaxDynamicSharedMemorySize, SMEM_BYTES);

    // 1. prep
    {
        int total = 640 * 128 + 384 * 256 + 640;
        prep_kernel<<<(total + 255) / 256, 256>>>(w_in, b_in, w_out, b_out, w_ih, w_hh, b_hh);
    }
    // 2. gather
    {
        long long total4 = (long long)Mrows * 32;
        gather_kernel<<<(int)((total4 + 255) / 256), 256>>>(x, emb);
    }
    // 3. big = hidden_r @ W1^T + bias1  (n<256 -> ht rounded transposed, else gh)
    mma_gemm<1><<<dim3(5, Mrows / 256, 1), 256, SMEM_BYTES>>>(
        p_hidden_r, 128, Mrows, 0,
        p_W1, 128, 0,
        p_bias1, nullptr,
        p_gh, 384, 0, 256,
        p_ht, 128);
    // 4. inputs = [A_lo@h_in + b_iah | A_hi@h_out + b_oah]  (1 m-tile per batch)
    mma_gemm<2><<<dim3(2, 1, Bsz), 256, SMEM_BYTES>>>(
        Amat, 2 * Nn, Nn, (long long)Nn * 2 * Nn,
        p_ht, Nn, 25600,
        b_iah, b_oah,
        p_inputs, 256, (long long)Nn * 256, 0,
        nullptr, Nn);
    // 5. gi = inputs @ w_ih^T + b_ih
    mma_gemm<0><<<dim3(3, Mrows / 256, 1), 256, SMEM_BYTES>>>(
        p_inputs, 256, Mrows, 0,
        p_W2r, 256, 0,
        b_ih, nullptr,
        p_gi, 384, 0, 0,
        nullptr, 256);
    // 6. gates
    {
        long long total = (long long)Mrows * 128;
        gates_kernel<<<(int)((total + 255) / 256), 256>>>(out);
    }
}